// round 13
// baseline (speedup 1.0000x reference)
#include <cuda_runtime.h>
#include <cuda_fp16.h>
#include <cstdint>

// Problem constants (fixed shapes in reference)
#define F_DIM 16384
#define D_DIM 768
#define N_DIM 1024      // B*S = 2*512
#define M_CONN 262144
#define IPC 8
#define BATCH 8
#define STAGE 256
#define V1_END 144384   // values split: > seg(F/2)=131072+-256 by ~50 sigma
#define F_HALF 8192
#define SPMM_GRID 888   // 148 SMs x 6 resident CTAs

// Scratch
__device__ uint2 g_XTh[(size_t)F_DIM * N_DIM / 4];   // [F][N] halfs
__device__ uint2 g_UTh[(size_t)F_DIM * D_DIM / 4];   // [F][D] halfs
__device__ float g_vals[M_CONN];
__device__ int   g_seg[F_DIM + 1];

// ---------------------------------------------------------------------------
__global__ __launch_bounds__(256) void seg_build_kernel(const int* __restrict__ iidx)
{
    int t = blockIdx.x * 256 + threadIdx.x;
    if (t > F_DIM) return;
    int lo = 0, hi = M_CONN;
    while (lo < hi) {
        int mid = (lo + hi) >> 1;
        if (__ldg(iidx + mid) < t) lo = mid + 1; else hi = mid;
    }
    g_seg[t] = lo;
}

// ---------------------------------------------------------------------------
// Vectorized tiled transpose with fp32 -> fp16 convert: dst[C,R] <- src[R,C].
// ---------------------------------------------------------------------------
__global__ __launch_bounds__(256) void transpose4h_kernel(
    const float4* __restrict__ src, __half* __restrict__ dst, int R)
{
    __shared__ float tile[32][132];
    const int C = F_DIM;
    const int c0 = blockIdx.x * 128;
    const int r0 = blockIdx.y * 32;
    const int tx = threadIdx.x, ty = threadIdx.y;

#pragma unroll
    for (int dy = 0; dy < 32; dy += 8) {
        int row = ty + dy;
        float4 v = __ldg(src + ((size_t)(r0 + row) * C + c0) / 4 + tx);
        *(float4*)&tile[row][4 * tx] = v;
    }
    __syncthreads();

    const int t = ty * 32 + tx;
#pragma unroll
    for (int it = 0; it < 4; it++) {
        int gid = it * 256 + t;
        int rr = gid & 7;
        int cc = gid >> 3;
        __half2 lo = __floats2half2_rn(tile[4 * rr + 0][cc], tile[4 * rr + 1][cc]);
        __half2 hi = __floats2half2_rn(tile[4 * rr + 2][cc], tile[4 * rr + 3][cc]);
        uint2 o;
        o.x = reinterpret_cast<unsigned&>(lo);
        o.y = reinterpret_cast<unsigned&>(hi);
        *(uint2*)(dst + (size_t)(c0 + cc) * R + r0 + 4 * rr) = o;
    }
}

// ---------------------------------------------------------------------------
// values[m] = dot(E[i_m, :], UTh[j_m, :]) over D=768.  One warp per m.
// E fp32 (L1-resident via sorted-i reuse), UT fp16; fp32 accumulate.
// ---------------------------------------------------------------------------
__global__ __launch_bounds__(256) void values_kernel(
    const float* __restrict__ E,
    const int* __restrict__ iidx,
    const int* __restrict__ jidx,
    float* __restrict__ vals,
    int m0, int m1)
{
    int warp = threadIdx.x >> 5;
    int lane = threadIdx.x & 31;
    int m = m0 + blockIdx.x * 8 + warp;
    if (m >= m1) return;
    int i = __ldg(iidx + m);
    int j = __ldg(jidx + m);
    const float4* e = (const float4*)(E + (size_t)i * D_DIM);
    const uint2*  u = g_UTh + (size_t)j * (D_DIM / 4);
    float s = 0.f;
#pragma unroll
    for (int t = 0; t < D_DIM / 128; t++) {   // 6 iters
        float4 a = __ldg(e + lane + 32 * t);
        uint2  braw = __ldg(u + lane + 32 * t);
        float2 b01 = __half22float2(reinterpret_cast<__half2&>(braw.x));
        float2 b23 = __half22float2(reinterpret_cast<__half2&>(braw.y));
        s += a.x * b01.x + a.y * b01.y + a.z * b23.x + a.w * b23.y;
    }
#pragma unroll
    for (int off = 16; off; off >>= 1)
        s += __shfl_xor_sync(0xffffffffu, s, off);
    if (lane == 0) vals[m] = s;
}

// ---------------------------------------------------------------------------
// Segmented SpMM, persistent grid-stride over i-octets in [i_base, i_end).
// ---------------------------------------------------------------------------
__global__ __launch_bounds__(256, 6) void spmm_fused_kernel(
    const int* __restrict__ jidx,
    float* __restrict__ out,
    int i_base, int i_end)
{
    __shared__ int    seg[IPC + 1];
    __shared__ float4 srow[IPC][N_DIM / 4];   // 32 KB
    __shared__ uint2  sjv[STAGE];             // {j, v bits}

    const int tid = threadIdx.x;
    const float4 zero = make_float4(0.f, 0.f, 0.f, 0.f);
    const uint2* XT = g_XTh;
    const int n_oct = (i_end - i_base) / IPC;

    for (int oct = blockIdx.x; oct < n_oct; oct += gridDim.x) {
        const int i_lo = i_base + oct * IPC;

#pragma unroll
        for (int r = 0; r < IPC; r++) srow[r][tid] = zero;
        if (tid <= IPC) seg[tid] = __ldg(g_seg + i_lo + tid);
        __syncthreads();

        const int mA = seg[0], mB = seg[IPC];

        float4 acc = zero;
        int r = 0;
        int next = seg[1];

        for (int base = mA; base < mB; base += STAGE) {
            {
                int m = base + tid;
                int mm = m < mB ? m : mB - 1;
                uint2 e;
                e.x = (unsigned)__ldg(jidx + mm);
                e.y = (m < mB) ? __float_as_uint(__ldg(g_vals + mm)) : 0u;
                sjv[tid] = e;
            }
            __syncthreads();

            const int cnt = (mB - base < STAGE) ? (mB - base) : STAGE;
            for (int k0 = 0; k0 < cnt; k0 += BATCH) {
                uint2 jv[BATCH];
#pragma unroll
                for (int k = 0; k < BATCH; k++) jv[k] = sjv[k0 + k];
                uint2 xx[BATCH];
#pragma unroll
                for (int k = 0; k < BATCH; k++)
                    xx[k] = __ldg(XT + (size_t)jv[k].x * (N_DIM / 4) + tid);
#pragma unroll
                for (int k = 0; k < BATCH; k++) {
                    int m_k = base + k0 + k;
                    while (m_k >= next) {        // uniform; ~1 in 16 m's
                        srow[r][tid] = acc;
                        acc = zero;
                        r++;
                        next = (r < IPC) ? seg[r + 1] : 0x7fffffff;
                    }
                    float v = __uint_as_float(jv[k].y);
                    float2 f01 = __half22float2(reinterpret_cast<__half2&>(xx[k].x));
                    float2 f23 = __half22float2(reinterpret_cast<__half2&>(xx[k].y));
                    acc.x += v * f01.x;
                    acc.y += v * f01.y;
                    acc.z += v * f23.x;
                    acc.w += v * f23.y;
                }
            }
            __syncthreads();
        }
        if (r < IPC) srow[r][tid] = acc;
        __syncthreads();

        // Epilogue: out[n][i_lo..i_lo+7] <- srow[0..7][n]
        const float* sr = (const float*)srow;
#pragma unroll
        for (int t = 0; t < 4; t++) {
            int n = tid + 256 * t;
            float4 a, b;
            a.x = sr[0 * N_DIM + n]; a.y = sr[1 * N_DIM + n];
            a.z = sr[2 * N_DIM + n]; a.w = sr[3 * N_DIM + n];
            b.x = sr[4 * N_DIM + n]; b.y = sr[5 * N_DIM + n];
            b.z = sr[6 * N_DIM + n]; b.w = sr[7 * N_DIM + n];
            float* o = out + (size_t)n * F_DIM + i_lo;
            *(float4*)o = a;
            *(float4*)(o + 4) = b;
        }
        __syncthreads();   // srow reuse across octets
    }
}

// ---------------------------------------------------------------------------
// Host-side stream/event objects (created once; NOT device memory).
static cudaStream_t g_s2 = nullptr;
static cudaEvent_t  g_evRoot = nullptr, g_evV1 = nullptr, g_evXT = nullptr, g_evS1 = nullptr;

extern "C" void kernel_launch(void* const* d_in, const int* in_sizes, int n_in,
                              void* d_out, int out_size)
{
    const float* up_facts     = (const float*)d_in[0];  // [N, F]
    const float* down_encoder = (const float*)d_in[1];  // [F, D]
    const float* up_decoder   = (const float*)d_in[2];  // [D, F]
    const int*   i_indices    = (const int*)d_in[3];    // [M] sorted int32
    const int*   j_indices    = (const int*)d_in[4];    // [M]
    float* out = (float*)d_out;                          // [N, F]

    if (!g_s2) {
        cudaStreamCreateWithFlags(&g_s2, cudaStreamNonBlocking);
        cudaEventCreateWithFlags(&g_evRoot, cudaEventDisableTiming);
        cudaEventCreateWithFlags(&g_evV1,   cudaEventDisableTiming);
        cudaEventCreateWithFlags(&g_evXT,   cudaEventDisableTiming);
        cudaEventCreateWithFlags(&g_evS1,   cudaEventDisableTiming);
    }

    uint2* xt;   cudaGetSymbolAddress((void**)&xt,   g_XTh);
    uint2* ut;   cudaGetSymbolAddress((void**)&ut,   g_UTh);
    float* vals; cudaGetSymbolAddress((void**)&vals, g_vals);

    // fork
    cudaEventRecord(g_evRoot, 0);
    cudaStreamWaitEvent(g_s2, g_evRoot, 0);

    // stream2: seg pointers + XT transpose (prereqs of s-chunks)
    seg_build_kernel<<<(F_DIM + 256) / 256, 256, 0, g_s2>>>(i_indices);
    transpose4h_kernel<<<dim3(F_DIM / 128, N_DIM / 32), dim3(32, 8), 0, g_s2>>>(
        (const float4*)up_facts, (__half*)xt, N_DIM);
    cudaEventRecord(g_evXT, g_s2);

    // stream0: UT transpose -> v1 -> v2
    transpose4h_kernel<<<dim3(F_DIM / 128, D_DIM / 32), dim3(32, 8)>>>(
        (const float4*)up_decoder, (__half*)ut, D_DIM);
    values_kernel<<<V1_END / 8, 256>>>(down_encoder, i_indices, j_indices, vals,
                                       0, V1_END);
    cudaEventRecord(g_evV1, 0);
    values_kernel<<<(M_CONN - V1_END) / 8, 256>>>(down_encoder, i_indices, j_indices,
                                                  vals, V1_END, M_CONN);

    // stream2: s1 (i < F/2) — overlaps with v2 on stream0
    cudaStreamWaitEvent(g_s2, g_evV1, 0);
    spmm_fused_kernel<<<SPMM_GRID, 256, 0, g_s2>>>(j_indices, out, 0, F_HALF);
    cudaEventRecord(g_evS1, g_s2);

    // stream0: s2 (i >= F/2) after v2; needs XT+seg from stream2
    cudaStreamWaitEvent(0, g_evXT, 0);
    spmm_fused_kernel<<<SPMM_GRID, 256>>>(j_indices, out, F_HALF, F_DIM);

    // join s1 branch
    cudaStreamWaitEvent(0, g_evS1, 0);
}

// round 14
// speedup vs baseline: 1.1606x; 1.1606x over previous
#include <cuda_runtime.h>
#include <cuda_fp16.h>
#include <cstdint>

// Problem constants (fixed shapes in reference)
#define F_DIM 16384
#define D_DIM 768
#define N_DIM 1024      // B*S = 2*512
#define M_CONN 262144
#define IPC 8
#define BATCH 8
#define STAGE 256
#define F_HALF 8192

// Scratch
__device__ uint2 g_XTh[(size_t)F_DIM * N_DIM / 4];   // [F][N] halfs
__device__ uint2 g_UTh[(size_t)F_DIM * D_DIM / 4];   // [F][D] halfs
__device__ float g_vals[M_CONN];
__device__ int   g_seg[F_DIM + 1];

// ---------------------------------------------------------------------------
__global__ __launch_bounds__(256) void seg_build_kernel(const int* __restrict__ iidx)
{
    int t = blockIdx.x * 256 + threadIdx.x;
    if (t > F_DIM) return;
    int lo = 0, hi = M_CONN;
    while (lo < hi) {
        int mid = (lo + hi) >> 1;
        if (__ldg(iidx + mid) < t) lo = mid + 1; else hi = mid;
    }
    g_seg[t] = lo;
}

// ---------------------------------------------------------------------------
// Vectorized tiled transpose with fp32 -> fp16 convert: dst[C,R] <- src[R,C].
// ---------------------------------------------------------------------------
__global__ __launch_bounds__(256) void transpose4h_kernel(
    const float4* __restrict__ src, __half* __restrict__ dst, int R)
{
    __shared__ float tile[32][132];
    const int C = F_DIM;
    const int c0 = blockIdx.x * 128;
    const int r0 = blockIdx.y * 32;
    const int tx = threadIdx.x, ty = threadIdx.y;

#pragma unroll
    for (int dy = 0; dy < 32; dy += 8) {
        int row = ty + dy;
        float4 v = __ldg(src + ((size_t)(r0 + row) * C + c0) / 4 + tx);
        *(float4*)&tile[row][4 * tx] = v;
    }
    __syncthreads();

    const int t = ty * 32 + tx;
#pragma unroll
    for (int it = 0; it < 4; it++) {
        int gid = it * 256 + t;
        int rr = gid & 7;
        int cc = gid >> 3;
        __half2 lo = __floats2half2_rn(tile[4 * rr + 0][cc], tile[4 * rr + 1][cc]);
        __half2 hi = __floats2half2_rn(tile[4 * rr + 2][cc], tile[4 * rr + 3][cc]);
        uint2 o;
        o.x = reinterpret_cast<unsigned&>(lo);
        o.y = reinterpret_cast<unsigned&>(hi);
        *(uint2*)(dst + (size_t)(c0 + cc) * R + r0 + 4 * rr) = o;
    }
}

// ---------------------------------------------------------------------------
// values, warp-per-segment: warp owns i = i0 + bid*8 + warp; loads E[i] row
// into 24 regs ONCE, then computes all dots of its segment (m-loop, x2
// unrolled so the two shuffle-reduce chains interleave).
// ---------------------------------------------------------------------------
__global__ __launch_bounds__(256) void values_seg_kernel(
    const float* __restrict__ E,
    const int* __restrict__ jidx,
    float* __restrict__ vals,
    int i0)
{
    const int warp = threadIdx.x >> 5;
    const int lane = threadIdx.x & 31;
    const int i = i0 + blockIdx.x * 8 + warp;

    const int mS = __ldg(g_seg + i);
    const int mE = __ldg(g_seg + i + 1);
    if (mS >= mE) return;

    // E row -> registers (lane owns elements (lane+32t)*4 .. +3, t = 0..5)
    float4 er[6];
    const float4* e = (const float4*)(E + (size_t)i * D_DIM);
#pragma unroll
    for (int t = 0; t < 6; t++) er[t] = __ldg(e + lane + 32 * t);

    int m = mS;
    for (; m + 2 <= mE; m += 2) {
        int j0 = __ldg(jidx + m);
        int j1 = __ldg(jidx + m + 1);
        const uint2* u0 = g_UTh + (size_t)j0 * (D_DIM / 4);
        const uint2* u1 = g_UTh + (size_t)j1 * (D_DIM / 4);
        float sa = 0.f, sb = 0.f;
#pragma unroll
        for (int t = 0; t < 6; t++) {
            uint2 b0 = __ldg(u0 + lane + 32 * t);
            uint2 b1 = __ldg(u1 + lane + 32 * t);
            float2 a01 = __half22float2(reinterpret_cast<__half2&>(b0.x));
            float2 a23 = __half22float2(reinterpret_cast<__half2&>(b0.y));
            float2 c01 = __half22float2(reinterpret_cast<__half2&>(b1.x));
            float2 c23 = __half22float2(reinterpret_cast<__half2&>(b1.y));
            sa += er[t].x * a01.x + er[t].y * a01.y + er[t].z * a23.x + er[t].w * a23.y;
            sb += er[t].x * c01.x + er[t].y * c01.y + er[t].z * c23.x + er[t].w * c23.y;
        }
#pragma unroll
        for (int off = 16; off; off >>= 1) {
            sa += __shfl_xor_sync(0xffffffffu, sa, off);
            sb += __shfl_xor_sync(0xffffffffu, sb, off);
        }
        if (lane == 0) { vals[m] = sa; vals[m + 1] = sb; }
    }
    if (m < mE) {
        int j = __ldg(jidx + m);
        const uint2* u = g_UTh + (size_t)j * (D_DIM / 4);
        float s = 0.f;
#pragma unroll
        for (int t = 0; t < 6; t++) {
            uint2 b = __ldg(u + lane + 32 * t);
            float2 a01 = __half22float2(reinterpret_cast<__half2&>(b.x));
            float2 a23 = __half22float2(reinterpret_cast<__half2&>(b.y));
            s += er[t].x * a01.x + er[t].y * a01.y + er[t].z * a23.x + er[t].w * a23.y;
        }
#pragma unroll
        for (int off = 16; off; off >>= 1)
            s += __shfl_xor_sync(0xffffffffu, s, off);
        if (lane == 0) vals[m] = s;
    }
}

// ---------------------------------------------------------------------------
// Segmented SpMM over i in [i_base + bid*IPC, +IPC); seg pointers precomputed.
// (R9-identical.)
// ---------------------------------------------------------------------------
__global__ __launch_bounds__(256) void spmm_fused_kernel(
    const int* __restrict__ jidx,
    float* __restrict__ out,
    int i_base)
{
    __shared__ int    seg[IPC + 1];
    __shared__ float4 srow[IPC][N_DIM / 4];   // 32 KB
    __shared__ uint2  sjv[STAGE];             // {j, v bits}

    const int i_lo = i_base + blockIdx.x * IPC;
    const int tid = threadIdx.x;
    const float4 zero = make_float4(0.f, 0.f, 0.f, 0.f);

#pragma unroll
    for (int r = 0; r < IPC; r++) srow[r][tid] = zero;

    if (tid <= IPC) seg[tid] = __ldg(g_seg + i_lo + tid);
    __syncthreads();

    const int mA = seg[0], mB = seg[IPC];
    const uint2* XT = g_XTh;

    float4 acc = zero;
    int r = 0;
    int next = seg[1];

    for (int base = mA; base < mB; base += STAGE) {
        {
            int m = base + tid;
            int mm = m < mB ? m : mB - 1;
            uint2 e;
            e.x = (unsigned)__ldg(jidx + mm);
            e.y = (m < mB) ? __float_as_uint(__ldg(g_vals + mm)) : 0u;
            sjv[tid] = e;
        }
        __syncthreads();

        const int cnt = (mB - base < STAGE) ? (mB - base) : STAGE;
        for (int k0 = 0; k0 < cnt; k0 += BATCH) {
            uint2 jv[BATCH];
#pragma unroll
            for (int k = 0; k < BATCH; k++) jv[k] = sjv[k0 + k];
            uint2 xx[BATCH];
#pragma unroll
            for (int k = 0; k < BATCH; k++)
                xx[k] = __ldg(XT + (size_t)jv[k].x * (N_DIM / 4) + tid);
#pragma unroll
            for (int k = 0; k < BATCH; k++) {
                int m_k = base + k0 + k;
                while (m_k >= next) {        // uniform; ~1 in 16 m's
                    srow[r][tid] = acc;
                    acc = zero;
                    r++;
                    next = (r < IPC) ? seg[r + 1] : 0x7fffffff;
                }
                float v = __uint_as_float(jv[k].y);
                float2 f01 = __half22float2(reinterpret_cast<__half2&>(xx[k].x));
                float2 f23 = __half22float2(reinterpret_cast<__half2&>(xx[k].y));
                acc.x += v * f01.x;
                acc.y += v * f01.y;
                acc.z += v * f23.x;
                acc.w += v * f23.y;
            }
        }
        __syncthreads();
    }
    if (r < IPC) srow[r][tid] = acc;
    __syncthreads();

    // Epilogue: out[n][i_lo..i_lo+7] <- srow[0..7][n]
    const float* sr = (const float*)srow;
#pragma unroll
    for (int t = 0; t < 4; t++) {
        int n = tid + 256 * t;
        float4 a, b;
        a.x = sr[0 * N_DIM + n]; a.y = sr[1 * N_DIM + n];
        a.z = sr[2 * N_DIM + n]; a.w = sr[3 * N_DIM + n];
        b.x = sr[4 * N_DIM + n]; b.y = sr[5 * N_DIM + n];
        b.z = sr[6 * N_DIM + n]; b.w = sr[7 * N_DIM + n];
        float* o = out + (size_t)n * F_DIM + i_lo;
        *(float4*)o = a;
        *(float4*)(o + 4) = b;
    }
}

// ---------------------------------------------------------------------------
// Host-side stream/event objects (created once; NOT device memory).
static cudaStream_t g_s2 = nullptr;
static cudaEvent_t  g_evRoot = nullptr, g_evV1 = nullptr, g_evXT = nullptr, g_evS1 = nullptr;

extern "C" void kernel_launch(void* const* d_in, const int* in_sizes, int n_in,
                              void* d_out, int out_size)
{
    const float* up_facts     = (const float*)d_in[0];  // [N, F]
    const float* down_encoder = (const float*)d_in[1];  // [F, D]
    const float* up_decoder   = (const float*)d_in[2];  // [D, F]
    const int*   i_indices    = (const int*)d_in[3];    // [M] sorted int32
    const int*   j_indices    = (const int*)d_in[4];    // [M]
    float* out = (float*)d_out;                          // [N, F]

    if (!g_s2) {
        cudaStreamCreateWithFlags(&g_s2, cudaStreamNonBlocking);
        cudaEventCreateWithFlags(&g_evRoot, cudaEventDisableTiming);
        cudaEventCreateWithFlags(&g_evV1,   cudaEventDisableTiming);
        cudaEventCreateWithFlags(&g_evXT,   cudaEventDisableTiming);
        cudaEventCreateWithFlags(&g_evS1,   cudaEventDisableTiming);
    }

    uint2* xt;   cudaGetSymbolAddress((void**)&xt,   g_XTh);
    uint2* ut;   cudaGetSymbolAddress((void**)&ut,   g_UTh);
    float* vals; cudaGetSymbolAddress((void**)&vals, g_vals);

    // fork
    cudaEventRecord(g_evRoot, 0);
    cudaStreamWaitEvent(g_s2, g_evRoot, 0);

    // stream2: XT transpose (prereq of s1/s2)
    transpose4h_kernel<<<dim3(F_DIM / 128, N_DIM / 32), dim3(32, 8), 0, g_s2>>>(
        (const float4*)up_facts, (__half*)xt, N_DIM);
    cudaEventRecord(g_evXT, g_s2);

    // stream0: seg -> UT transpose -> v1 (segments [0, F/2)) -> v2
    seg_build_kernel<<<(F_DIM + 256) / 256, 256>>>(i_indices);
    transpose4h_kernel<<<dim3(F_DIM / 128, D_DIM / 32), dim3(32, 8)>>>(
        (const float4*)up_decoder, (__half*)ut, D_DIM);
    values_seg_kernel<<<F_HALF / 8, 256>>>(down_encoder, j_indices, vals, 0);
    cudaEventRecord(g_evV1, 0);
    values_seg_kernel<<<F_HALF / 8, 256>>>(down_encoder, j_indices, vals, F_HALF);

    // stream2: s1 (i < F/2) — overlaps with v2 on stream0
    cudaStreamWaitEvent(g_s2, g_evV1, 0);
    spmm_fused_kernel<<<F_HALF / IPC, 256, 0, g_s2>>>(j_indices, out, 0);
    cudaEventRecord(g_evS1, g_s2);

    // stream0: s2 (i >= F/2) after v2; needs XT from stream2
    cudaStreamWaitEvent(0, g_evXT, 0);
    spmm_fused_kernel<<<F_HALF / IPC, 256>>>(j_indices, out, F_HALF);

    // join s1 branch
    cudaStreamWaitEvent(0, g_evS1, 0);
}